// round 11
// baseline (speedup 1.0000x reference)
#include <cuda_runtime.h>
#include <cstdint>

#define EPSF 1e-5f
#define SCALE 0.17677669529663687f

// scratch
__device__ float g_qn[2*384*128];
__device__ float g_kn[2*384*128];
__device__ float g_vn[2*384*128];
__device__ float g_ao[2*384*128];
__device__ float g_Pc[2*384*64];
__device__ float g_Pd[2*384*64];

// packed f32x2 FMA: d = a*b + d  (per 32-bit half)
__device__ __forceinline__ void fma2(unsigned long long &d, unsigned long long a, unsigned long long b){
    asm("fma.rn.f32x2 %0, %1, %2, %3;" : "=l"(d) : "l"(a), "l"(b), "l"(d));
}
__device__ __forceinline__ float hsum2(unsigned long long v){
    return __uint_as_float((unsigned)v) + __uint_as_float((unsigned)(v>>32));
}

// ============ k_qkv: 8 rows/CTA, smem-staged weights, 4-row blocking ============
#define QKV_SMEM (51744*4)
__global__ void __launch_bounds__(256) k_qkv(const float* __restrict__ x,
    const float* __restrict__ wnq, const float* __restrict__ wnk, const float* __restrict__ wnv){
    extern __shared__ float sm[];
    float* sWq = sm;             // 128*132
    float* sWk = sm + 16896;
    float* sWv = sm + 33792;
    float* sX  = sm + 50688;     // 8*132
    int tid = threadIdx.x;
    for (int idx=tid; idx<4096; idx+=256){
        int o = idx>>5, c4 = idx&31;
        *(float4*)(sWq + o*132 + c4*4) = *(const float4*)(wnq + o*128 + c4*4);
        *(float4*)(sWk + o*132 + c4*4) = *(const float4*)(wnk + o*128 + c4*4);
        *(float4*)(sWv + o*132 + c4*4) = *(const float4*)(wnv + o*128 + c4*4);
    }
    int r0 = blockIdx.x*8;
    { int r = tid>>5, c4 = tid&31;
      *(float4*)(sX + r*132 + c4*4) = *(const float4*)(x + (size_t)(r0+r)*128 + c4*4); }
    __syncthreads();
    int o = tid&127, g = tid>>7;
    float aq[4]={0,0,0,0}, ak[4]={0,0,0,0}, av[4]={0,0,0,0};
#pragma unroll 4
    for (int c4=0;c4<32;++c4){
        float4 wq = *(const float4*)(sWq + o*132 + c4*4);
        float4 wk = *(const float4*)(sWk + o*132 + c4*4);
        float4 wv = *(const float4*)(sWv + o*132 + c4*4);
#pragma unroll
        for (int rr=0;rr<4;++rr){
            float4 a = *(const float4*)(sX + (g*4+rr)*132 + c4*4);
            aq[rr] += wq.x*a.x+wq.y*a.y+wq.z*a.z+wq.w*a.w;
            ak[rr] += wk.x*a.x+wk.y*a.y+wk.z*a.z+wk.w*a.w;
            av[rr] += wv.x*a.x+wv.y*a.y+wv.z*a.z+wv.w*a.w;
        }
    }
#pragma unroll
    for (int rr=0;rr<4;++rr){
        int r = r0 + g*4 + rr;
        g_qn[r*128+o]=aq[rr]; g_kn[r*128+o]=ak[rr]; g_vn[r*128+o]=av[rr];
    }
}

// ============ k_attn: one CTA per (b,i) ============
#define ATTN_SMEM (22784*4)
__global__ void __launch_bounds__(256) k_attn(const float* __restrict__ adj,
    const float* __restrict__ weq, const float* __restrict__ wek, const float* __restrict__ wev){
    extern __shared__ float sm[];
    float* sW = sm;
    float* sA = sm + 17408;
    float* sS = sm + 19584;
    float* sQ = sm + 22656;
    int bi = blockIdx.x, b = bi/384;
    int tid = threadIdx.x;
    int to = tid&31, tp = tid>>5;      // tp = warp id
    for (int idx=tid; idx<4096; idx+=256){
        int o = idx>>4, c4 = idx&15;
        float4 v = (o<128) ? *(const float4*)(weq + o*64 + c4*4)
                           : *(const float4*)(wek + (o-128)*64 + c4*4);
        *(float4*)(sW + o*68 + c4*4) = v;
    }
    if (tid<128) sQ[tid] = g_qn[(size_t)bi*128 + tid];
    const float* adj_i = adj + (size_t)bi*24576;
    __syncthreads();

    // ---- phase 1: eq/ek GEMM (packed f32x2) + scores ----
    for (int jt=0; jt<12; ++jt){
        int j0 = jt*32;
        for (int idx=tid; idx<512; idx+=256){
            int p = idx>>4, c4 = idx&15;
            *(float4*)(sA + p*68 + c4*4) = *(const float4*)(adj_i + (size_t)(j0+p)*64 + c4*4);
        }
        __syncthreads();
        unsigned long long acc[4][8];
#pragma unroll
        for (int p=0;p<4;++p)
#pragma unroll
            for (int o=0;o<8;++o) acc[p][o]=0ull;
#pragma unroll 2
        for (int c4=0;c4<16;++c4){
            ulonglong2 a[4], w[8];
#pragma unroll
            for (int k=0;k<4;++k) a[k] = *(const ulonglong2*)(sA + (tp*4+k)*68 + c4*4);
#pragma unroll
            for (int k=0;k<8;++k) w[k] = *(const ulonglong2*)(sW + (k*32+to)*68 + c4*4);
#pragma unroll
            for (int p=0;p<4;++p)
#pragma unroll
                for (int o=0;o<8;++o){
                    fma2(acc[p][o], a[p].x, w[o].x);
                    fma2(acc[p][o], a[p].y, w[o].y);
                }
        }
#pragma unroll
        for (int pp=0;pp<4;++pp){
            int j = j0 + tp*4 + pp;
            const float* kr = g_kn + (size_t)(b*384+j)*128;
#pragma unroll
            for (int m=0;m<4;++m){
                int d = m*32 + to;
                float eq = sQ[d] + hsum2(acc[pp][m]);
                float ek = __ldg(&kr[d]) + hsum2(acc[pp][m+4]);
                float pr = eq*ek;
                pr += __shfl_xor_sync(0xffffffffu, pr, 1);
                pr += __shfl_xor_sync(0xffffffffu, pr, 2);
                pr += __shfl_xor_sync(0xffffffffu, pr, 4);
                pr += __shfl_xor_sync(0xffffffffu, pr, 8);
                if ((to&15)==0) sS[(2*m + (to>>4))*384 + j] = pr*SCALE;
            }
        }
        __syncthreads();
    }

    float* sWV = sm;
    float* sAW = sm + 8192;
    float* sOV = sm + 12288;
    float* sTOT= sm + 13312;
    float* sOVT= sm + 13824;
    for (int idx=tid; idx<8192; idx+=256) sWV[idx]=wev[idx];
    __syncthreads();

    // ---- phase 2: softmax, warp = head ----
    {
        int w = tp, l = to;
        float vals[12]; float m=-1e30f;
#pragma unroll
        for (int q=0;q<12;++q){ vals[q]=sS[w*384+q*32+l]; m=fmaxf(m,vals[q]); }
#pragma unroll
        for (int off=16;off;off>>=1) m=fmaxf(m,__shfl_xor_sync(0xffffffffu,m,off));
        float Z=0.f;
#pragma unroll
        for (int q=0;q<12;++q){ vals[q]=__expf(vals[q]-m); Z+=vals[q]; }
#pragma unroll
        for (int off=16;off;off>>=1) Z+=__shfl_xor_sync(0xffffffffu,Z,off);
        float inv=1.0f/Z;
#pragma unroll
        for (int q=0;q<12;++q) sS[w*384+q*32+l]=vals[q]*inv;
    }
    __syncthreads();

    // ---- phase 3: attn-weighted sums ----
    {
        int w = tp, l = to, h2l = l>>2;
        float aw0[8], aw1[8]; float4 ov = make_float4(0,0,0,0);
#pragma unroll
        for (int h=0;h<8;++h){ aw0[h]=0.f; aw1[h]=0.f; }
        for (int jj=0; jj<48; ++jj){
            int j=w*48+jj;
            float ah[8];
#pragma unroll
            for (int h=0;h<8;++h) ah[h]=sS[h*384+j];
            float2 av = ((const float2*)(adj_i + (size_t)j*64))[l];
#pragma unroll
            for (int h=0;h<8;++h){ aw0[h]+=ah[h]*av.x; aw1[h]+=ah[h]*av.y; }
            float4 vv = ((const float4*)(g_vn + (size_t)(b*384+j)*128))[l];
            float a = ah[h2l];
            ov.x+=a*vv.x; ov.y+=a*vv.y; ov.z+=a*vv.z; ov.w+=a*vv.w;
        }
#pragma unroll
        for (int h=0;h<8;++h){ sAW[(w*8+h)*64 + 2*l]=aw0[h]; sAW[(w*8+h)*64 + 2*l+1]=aw1[h]; }
        ((float4*)(sOV + w*128))[l]=ov;
    }
    __syncthreads();
    for (int idx=tid; idx<512; idx+=256){
        float s=0.f;
#pragma unroll
        for (int w2=0;w2<8;++w2) s+=sAW[w2*512+idx];
        sTOT[idx]=s;
    }
    if (tid<128){
        float s=0.f;
#pragma unroll
        for (int w2=0;w2<8;++w2) s+=sOV[w2*128+tid];
        sOVT[tid]=s;
    }
    __syncthreads();
    if (tid<128){
        int h=tid>>4;
        float acc=sOVT[tid];
#pragma unroll 8
        for (int c=0;c<64;++c){
            int cc=(c+tid)&63;
            acc += sWV[tid*64+cc]*sTOT[h*64+cc];
        }
        g_ao[(size_t)bi*128 + (tid&15)*8 + h] = acc;
    }
}

// ============ k_node: 8 rows/CTA, staged weights, 4-row blocking ============
#define NODE_SMEM (40160*4)
__global__ void __launch_bounds__(256) k_node(const float* __restrict__ x,
    const float* __restrict__ nfc1_w, const float* __restrict__ nfc1_b,
    const float* __restrict__ ln1_g, const float* __restrict__ ln1_b,
    const float* __restrict__ nfc2_w, const float* __restrict__ nfc2_b,
    const float* __restrict__ nfc3_w, const float* __restrict__ nfc3_b,
    const float* __restrict__ ln2_g, const float* __restrict__ ln2_b,
    const float* __restrict__ efc1_w, float* __restrict__ out_x){
    extern __shared__ float sm[];
    float* sW  = sm;
    float* sao = sm + 33792;
    float* sx  = sm + 34848;
    float* sx1 = sm + 35904;
    float* sh  = sm + 36960;
    float* sx2 = sm + 39040;
    float* sred= sm + 40096;
    int tid = threadIdx.x;
    int o = tid&127, g = tid>>7;
    int l = tid&31, wg = (tid>>5)&3;
    int r0 = blockIdx.x*8;
    { int r = tid>>5, c4 = tid&31;
      *(float4*)(sx  + r*132 + c4*4) = *(const float4*)(x    + (size_t)(r0+r)*128 + c4*4);
      *(float4*)(sao + r*132 + c4*4) = *(const float4*)(g_ao + (size_t)(r0+r)*128 + c4*4); }
    for (int idx=tid; idx<4096; idx+=256){
        int oo=idx>>5, c4=idx&31;
        *(float4*)(sW + oo*132 + c4*4) = *(const float4*)(nfc1_w + oo*128 + c4*4);
    }
    __syncthreads();
    float val[4];
    {
        float acc[4]; float bv = __ldg(&nfc1_b[o]);
#pragma unroll
        for (int rr=0;rr<4;++rr) acc[rr]=bv;
#pragma unroll 4
        for (int c4=0;c4<32;++c4){
            float4 w = *(const float4*)(sW + o*132 + c4*4);
#pragma unroll
            for (int rr=0;rr<4;++rr){
                float4 a = *(const float4*)(sao + (g*4+rr)*132 + c4*4);
                acc[rr] += w.x*a.x+w.y*a.y+w.z*a.z+w.w*a.w;
            }
        }
#pragma unroll
        for (int rr=0;rr<4;++rr) val[rr] = sx[(g*4+rr)*132+o] + acc[rr];
    }
#pragma unroll
    for (int rr=0;rr<4;++rr){
        float s=val[rr], s2=val[rr]*val[rr];
#pragma unroll
        for (int off=16;off;off>>=1){ s+=__shfl_xor_sync(0xffffffffu,s,off); s2+=__shfl_xor_sync(0xffffffffu,s2,off); }
        if (l==0){ sred[(g*4+rr)*8 + wg*2]=s; sred[(g*4+rr)*8 + wg*2+1]=s2; }
    }
    __syncthreads();
#pragma unroll
    for (int rr=0;rr<4;++rr){
        int r = g*4+rr;
        float S = sred[r*8]+sred[r*8+2]+sred[r*8+4]+sred[r*8+6];
        float S2= sred[r*8+1]+sred[r*8+3]+sred[r*8+5]+sred[r*8+7];
        float m = S*(1.f/128.f), var = S2*(1.f/128.f)-m*m, rs = rsqrtf(var+EPSF);
        sx1[r*132+o] = (val[rr]-m)*rs*__ldg(&ln1_g[o])+__ldg(&ln1_b[o]);
    }
    __syncthreads();
    for (int idx=tid; idx<8192; idx+=256){
        int oo=idx>>5, c4=idx&31;
        *(float4*)(sW + oo*132 + c4*4) = *(const float4*)(nfc2_w + oo*128 + c4*4);
    }
    __syncthreads();
    {
        float a0[4], a1[4];
        float b0=__ldg(&nfc2_b[o]), b1=__ldg(&nfc2_b[o+128]);
#pragma unroll
        for (int rr=0;rr<4;++rr){ a0[rr]=b0; a1[rr]=b1; }
#pragma unroll 4
        for (int c4=0;c4<32;++c4){
            float4 w0 = *(const float4*)(sW + o*132 + c4*4);
            float4 w1 = *(const float4*)(sW + (o+128)*132 + c4*4);
#pragma unroll
            for (int rr=0;rr<4;++rr){
                float4 a = *(const float4*)(sx1 + (g*4+rr)*132 + c4*4);
                a0[rr] += w0.x*a.x+w0.y*a.y+w0.z*a.z+w0.w*a.w;
                a1[rr] += w1.x*a.x+w1.y*a.y+w1.z*a.z+w1.w*a.w;
            }
        }
#pragma unroll
        for (int rr=0;rr<4;++rr){
            sh[(g*4+rr)*260 + o]       = fmaxf(a0[rr],0.f);
            sh[(g*4+rr)*260 + 128 + o] = fmaxf(a1[rr],0.f);
        }
    }
    __syncthreads();
    for (int idx=tid; idx<8192; idx+=256){
        int oo=idx>>6, c4=idx&63;
        *(float4*)(sW + oo*260 + c4*4) = *(const float4*)(nfc3_w + oo*256 + c4*4);
    }
    __syncthreads();
    {
        float acc[4]; float bv=__ldg(&nfc3_b[o]);
#pragma unroll
        for (int rr=0;rr<4;++rr) acc[rr]=bv;
#pragma unroll 4
        for (int c4=0;c4<64;++c4){
            float4 w = *(const float4*)(sW + o*260 + c4*4);
#pragma unroll
            for (int rr=0;rr<4;++rr){
                float4 a = *(const float4*)(sh + (g*4+rr)*260 + c4*4);
                acc[rr] += w.x*a.x+w.y*a.y+w.z*a.z+w.w*a.w;
            }
        }
#pragma unroll
        for (int rr=0;rr<4;++rr) val[rr] = sx1[(g*4+rr)*132+o] + acc[rr];
    }
#pragma unroll
    for (int rr=0;rr<4;++rr){
        float s=val[rr], s2=val[rr]*val[rr];
#pragma unroll
        for (int off=16;off;off>>=1){ s+=__shfl_xor_sync(0xffffffffu,s,off); s2+=__shfl_xor_sync(0xffffffffu,s2,off); }
        if (l==0){ sred[(g*4+rr)*8 + wg*2]=s; sred[(g*4+rr)*8 + wg*2+1]=s2; }
    }
    __syncthreads();
#pragma unroll
    for (int rr=0;rr<4;++rr){
        int r = g*4+rr;
        float S = sred[r*8]+sred[r*8+2]+sred[r*8+4]+sred[r*8+6];
        float S2= sred[r*8+1]+sred[r*8+3]+sred[r*8+5]+sred[r*8+7];
        float m = S*(1.f/128.f), var = S2*(1.f/128.f)-m*m, rs = rsqrtf(var+EPSF);
        float x2v = (val[rr]-m)*rs*__ldg(&ln2_g[o])+__ldg(&ln2_b[o]);
        sx2[r*132+o] = x2v;
        out_x[(size_t)(r0+r)*128+o] = x2v;
    }
    __syncthreads();
    for (int idx=tid; idx<4096; idx+=256){
        int o2=idx>>5, c4=idx&31;
        float4 v = (o2<64) ? *(const float4*)(efc1_w + o2*384 + 128 + c4*4)
                           : *(const float4*)(efc1_w + (o2-64)*384 + 256 + c4*4);
        *(float4*)(sW + o2*132 + c4*4) = v;
    }
    __syncthreads();
    {
        float acc[4]={0,0,0,0};
#pragma unroll 4
        for (int c4=0;c4<32;++c4){
            float4 w = *(const float4*)(sW + o*132 + c4*4);
#pragma unroll
            for (int rr=0;rr<4;++rr){
                float4 a = *(const float4*)(sx2 + (g*4+rr)*132 + c4*4);
                acc[rr] += w.x*a.x+w.y*a.y+w.z*a.z+w.w*a.w;
            }
        }
#pragma unroll
        for (int rr=0;rr<4;++rr){
            int r = r0 + g*4 + rr;
            if (o<64) g_Pc[(size_t)r*64+o]=acc[rr];
            else      g_Pd[(size_t)r*64+(o-64)]=acc[rr];
        }
    }
}

// ============ k_edge: 256 threads, 4x4 tile, packed f32x2 FMA, phase-split weights ============
// floats: sW 8704 @0 | AI 8704 | AJ 13056 | PC 17408 | Y 21760 | sB 26112(640) => 26752 (107KB)
#define EDGE_SMEM (26752*4)
__device__ __forceinline__ void gemm64(const float* __restrict__ sA, const float* __restrict__ sW,
                                       unsigned long long acc[4][4], int tp, int to){
#pragma unroll 4
    for (int c4=0;c4<16;++c4){
        ulonglong2 a[4], w[4];
#pragma unroll
        for (int k=0;k<4;++k) a[k] = *(const ulonglong2*)(sA + (tp*4+k)*68 + c4*4);
#pragma unroll
        for (int k=0;k<4;++k) w[k] = *(const ulonglong2*)(sW + (k*16+to)*68 + c4*4);
#pragma unroll
        for (int p=0;p<4;++p)
#pragma unroll
            for (int oo=0;oo<4;++oo){
                fma2(acc[p][oo], a[p].x, w[oo].x);
                fma2(acc[p][oo], a[p].y, w[oo].y);
            }
    }
}

__global__ void __launch_bounds__(256) k_edge(const float* __restrict__ adj,
    const float* __restrict__ efc1_w, const float* __restrict__ efc1_b,
    const float* __restrict__ efc2_w, const float* __restrict__ efc2_b,
    const float* __restrict__ eg1, const float* __restrict__ eb1,
    const float* __restrict__ efc3_w, const float* __restrict__ efc3_b,
    const float* __restrict__ efc4_w, const float* __restrict__ efc4_b,
    const float* __restrict__ eg2, const float* __restrict__ eb2,
    float* __restrict__ out_adj){
    extern __shared__ float sm[];
    float* sW   = sm;          // 8704, reloaded per phase
    float* sAI  = sm + 8704;   // later H3lo
    float* sAJ  = sm + 13056;  // later H1, later OUT
    float* sPC  = sm + 17408;  // later H3hi
    float* sY   = sm + 21760;
    float* sB   = sm + 26112;
    int tid = threadIdx.x;
    int to = tid&15, tp = tid>>4;     // tp in 0..15
    int bx = blockIdx.x;
    int bi = bx/6, jt = bx - bi*6;
    int b = bi/384, i = bi - b*384;
    int j0 = jt*64;
    const float* adjb = adj + (size_t)b*9437184;

    // phase A1 weights: W1a @0, W1b @4352
    for (int idx=tid; idx<1024; idx+=256){
        int o = idx>>4, c4 = idx&15;
        *(float4*)(sW        + o*68 + c4*4) = *(const float4*)(efc1_w + o*384 + c4*4);
        *(float4*)(sW + 4352 + o*68 + c4*4) = *(const float4*)(efc1_w + o*384 + 64 + c4*4);
    }
    // activations
    for (int idx=tid; idx<1024; idx+=256){
        int p = idx>>4, c4 = idx&15;
        *(float4*)(sAI + p*68 + c4*4) = *(const float4*)(adjb + ((size_t)i*384 + j0+p)*64 + c4*4);
        *(float4*)(sAJ + p*68 + c4*4) = *(const float4*)(adjb + ((size_t)(j0+p)*384 + i)*64 + c4*4);
        *(float4*)(sPC + p*68 + c4*4) = *(const float4*)(g_Pc + (size_t)(b*384 + j0+p)*64 + c4*4);
    }
    if (tid<64){
        sB[tid]=efc1_b[tid]; sB[64+tid]=efc2_b[tid]; sB[128+tid]=efc4_b[tid];
        sB[192+tid]=eg1[tid]; sB[256+tid]=eb1[tid]; sB[320+tid]=eg2[tid]; sB[384+tid]=eb2[tid];
        sB[576+tid]=g_Pd[(size_t)bi*64+tid];
    }
    if (tid<128) sB[448+tid]=efc3_b[tid];
    __syncthreads();

    unsigned long long acc[4][4];
    // ---- stage 1: h1 = relu(Wa*ai + Wb*aj + pc + pd + b1) ----
#pragma unroll
    for (int p=0;p<4;++p)
#pragma unroll
        for (int oo=0;oo<4;++oo) acc[p][oo]=0ull;
    gemm64(sAI, sW, acc, tp, to);
    gemm64(sAJ, sW + 4352, acc, tp, to);
    __syncthreads();   // all reads of sAJ + W1 done
    float* sH1 = sAJ;
#pragma unroll
    for (int p=0;p<4;++p){
        int pr = tp*4+p;
#pragma unroll
        for (int oo=0;oo<4;++oo){
            int o = oo*16+to;
            float h = hsum2(acc[p][oo]) + sB[o] + sB[576+o] + sPC[pr*68+o];
            sH1[pr*68+o] = fmaxf(h, 0.f);
        }
    }
    // phase A2 weights: W2 @0
    for (int idx=tid; idx<1024; idx+=256){
        int o = idx>>4, c4 = idx&15;
        *(float4*)(sW + o*68 + c4*4) = *(const float4*)(efc2_w + o*64 + c4*4);
    }
    __syncthreads();
    // ---- stage 2: adj1 = LN(ai + W2*h1 + b2) ----
#pragma unroll
    for (int p=0;p<4;++p)
#pragma unroll
        for (int oo=0;oo<4;++oo) acc[p][oo]=0ull;
    gemm64(sH1, sW, acc, tp, to);
#pragma unroll
    for (int p=0;p<4;++p){
        int pr = tp*4+p;
        float v[4], s=0.f, s2=0.f;
#pragma unroll
        for (int oo=0;oo<4;++oo){
            int o = oo*16+to;
            v[oo] = hsum2(acc[p][oo]) + sB[64+o] + sAI[pr*68+o];
            s += v[oo]; s2 += v[oo]*v[oo];
        }
        s  += __shfl_xor_sync(0xffffffffu,s,1);  s2 += __shfl_xor_sync(0xffffffffu,s2,1);
        s  += __shfl_xor_sync(0xffffffffu,s,2);  s2 += __shfl_xor_sync(0xffffffffu,s2,2);
        s  += __shfl_xor_sync(0xffffffffu,s,4);  s2 += __shfl_xor_sync(0xffffffffu,s2,4);
        s  += __shfl_xor_sync(0xffffffffu,s,8);  s2 += __shfl_xor_sync(0xffffffffu,s2,8);
        float m = s*(1.f/64.f), var = s2*(1.f/64.f)-m*m, rs = rsqrtf(var+EPSF);
#pragma unroll
        for (int oo=0;oo<4;++oo){
            int o = oo*16+to;
            sY[pr*68+o] = (v[oo]-m)*rs*sB[192+o]+sB[256+o];
        }
    }
    __syncthreads();   // W2/AI reads done, Y written
    // phase B weights: W3 (128 rows)
    for (int idx=tid; idx<2048; idx+=256){
        int o = idx>>4, c4 = idx&15;
        *(float4*)(sW + o*68 + c4*4) = *(const float4*)(efc3_w + o*64 + c4*4);
    }
    __syncthreads();
    // ---- stage 3: h3 = relu(W3*adj1 + b3) ----
    float* sH3lo = sAI;
    float* sH3hi = sPC;
#pragma unroll
    for (int p=0;p<4;++p)
#pragma unroll
        for (int oo=0;oo<4;++oo) acc[p][oo]=0ull;
    gemm64(sY, sW, acc, tp, to);
#pragma unroll
    for (int p=0;p<4;++p){
        int pr = tp*4+p;
#pragma unroll
        for (int oo=0;oo<4;++oo){
            int o = oo*16+to;
            sH3lo[pr*68+o] = fmaxf(hsum2(acc[p][oo]) + sB[448+o], 0.f);
        }
    }
#pragma unroll
    for (int p=0;p<4;++p)
#pragma unroll
        for (int oo=0;oo<4;++oo) acc[p][oo]=0ull;
    gemm64(sY, sW + 64*68, acc, tp, to);
#pragma unroll
    for (int p=0;p<4;++p){
        int pr = tp*4+p;
#pragma unroll
        for (int oo=0;oo<4;++oo){
            int o = oo*16+to;
            sH3hi[pr*68+o] = fmaxf(hsum2(acc[p][oo]) + sB[448+64+o], 0.f);
        }
    }
    __syncthreads();   // W3 reads done, H3 written
    // phase C weights: W4lo @0, W4hi @4352
    for (int idx=tid; idx<1024; idx+=256){
        int o = idx>>4, c4 = idx&15;
        *(float4*)(sW        + o*68 + c4*4) = *(const float4*)(efc4_w + o*128 + c4*4);
        *(float4*)(sW + 4352 + o*68 + c4*4) = *(const float4*)(efc4_w + o*128 + 64 + c4*4);
    }
    __syncthreads();
    // ---- stage 4: out = LN(adj1 + W4*h3 + b4) ----
#pragma unroll
    for (int p=0;p<4;++p)
#pragma unroll
        for (int oo=0;oo<4;++oo) acc[p][oo]=0ull;
    gemm64(sH3lo, sW, acc, tp, to);
    gemm64(sH3hi, sW + 4352, acc, tp, to);
    __syncthreads();   // H1 buffer (sAJ) fully dead; safe to overwrite as sOut
    float* sOut = sAJ;
#pragma unroll
    for (int p=0;p<4;++p){
        int pr = tp*4+p;
        float v[4], s=0.f, s2=0.f;
#pragma unroll
        for (int oo=0;oo<4;++oo){
            int o = oo*16+to;
            v[oo] = hsum2(acc[p][oo]) + sB[128+o] + sY[pr*68+o];
            s += v[oo]; s2 += v[oo]*v[oo];
        }
        s  += __shfl_xor_sync(0xffffffffu,s,1);  s2 += __shfl_xor_sync(0xffffffffu,s2,1);
        s  += __shfl_xor_sync(0xffffffffu,s,2);  s2 += __shfl_xor_sync(0xffffffffu,s2,2);
        s  += __shfl_xor_sync(0xffffffffu,s,4);  s2 += __shfl_xor_sync(0xffffffffu,s2,4);
        s  += __shfl_xor_sync(0xffffffffu,s,8);  s2 += __shfl_xor_sync(0xffffffffu,s2,8);
        float m = s*(1.f/64.f), var = s2*(1.f/64.f)-m*m, rs = rsqrtf(var+EPSF);
#pragma unroll
        for (int oo=0;oo<4;++oo){
            int o = oo*16+to;
            sOut[pr*68+o] = (v[oo]-m)*rs*sB[320+o]+sB[384+o];
        }
    }
    __syncthreads();
    for (int idx=tid; idx<1024; idx+=256){
        int p = idx>>4, c4 = idx&15;
        *(float4*)(out_adj + ((size_t)bi*384 + j0+p)*64 + c4*4) = *(const float4*)(sOut + p*68 + c4*4);
    }
}

extern "C" void kernel_launch(void* const* d_in, const int* in_sizes, int n_in,
                              void* d_out, int out_size){
    const float* x       = (const float*)d_in[0];
    const float* adj     = (const float*)d_in[1];
    const float* wnq     = (const float*)d_in[2];
    const float* wnk     = (const float*)d_in[3];
    const float* wnv     = (const float*)d_in[4];
    const float* weq     = (const float*)d_in[5];
    const float* wek     = (const float*)d_in[6];
    const float* wev     = (const float*)d_in[7];
    const float* nfc1_w  = (const float*)d_in[8];
    const float* nfc1_b  = (const float*)d_in[9];
    const float* ln1_g   = (const float*)d_in[10];
    const float* ln1_b   = (const float*)d_in[11];
    const float* nfc2_w  = (const float*)d_in[12];
    const float* nfc2_b  = (const float*)d_in[13];
    const float* nfc3_w  = (const float*)d_in[14];
    const float* nfc3_b  = (const float*)d_in[15];
    const float* ln2_g   = (const float*)d_in[16];
    const float* ln2_b   = (const float*)d_in[17];
    const float* efc1_w  = (const float*)d_in[18];
    const float* efc1_b  = (const float*)d_in[19];
    const float* efc2_w  = (const float*)d_in[20];
    const float* efc2_b  = (const float*)d_in[21];
    const float* eln1_g  = (const float*)d_in[22];
    const float* eln1_b  = (const float*)d_in[23];
    const float* efc3_w  = (const float*)d_in[24];
    const float* efc3_b  = (const float*)d_in[25];
    const float* efc4_w  = (const float*)d_in[26];
    const float* efc4_b  = (const float*)d_in[27];
    const float* eln2_g  = (const float*)d_in[28];
    const float* eln2_b  = (const float*)d_in[29];
    float* out_x   = (float*)d_out;
    float* out_adj = out_x + 2*384*128;

    cudaFuncSetAttribute(k_qkv,  cudaFuncAttributeMaxDynamicSharedMemorySize, QKV_SMEM);
    cudaFuncSetAttribute(k_attn, cudaFuncAttributeMaxDynamicSharedMemorySize, ATTN_SMEM);
    cudaFuncSetAttribute(k_node, cudaFuncAttributeMaxDynamicSharedMemorySize, NODE_SMEM);
    cudaFuncSetAttribute(k_edge, cudaFuncAttributeMaxDynamicSharedMemorySize, EDGE_SMEM);

    k_qkv<<<96,256,QKV_SMEM>>>(x, wnq, wnk, wnv);
    k_attn<<<768,256,ATTN_SMEM>>>(adj, weq, wek, wev);
    k_node<<<96,256,NODE_SMEM>>>(x, nfc1_w, nfc1_b, ln1_g, ln1_b, nfc2_w, nfc2_b,
                                 nfc3_w, nfc3_b, ln2_g, ln2_b, efc1_w, out_x);
    k_edge<<<4608,256,EDGE_SMEM>>>(adj, efc1_w, efc1_b, efc2_w, efc2_b,
                                   eln1_g, eln1_b, efc3_w, efc3_b,
                                   efc4_w, efc4_b, eln2_g, eln2_b, out_adj);
}

// round 13
// speedup vs baseline: 1.0278x; 1.0278x over previous
#include <cuda_runtime.h>
#include <cuda_bf16.h>
#include <cstdint>

#define EPSF 1e-5f
#define SCALE 0.17677669529663687f

__device__ float g_qn[2*384*128];
__device__ float g_kn[2*384*128];
__device__ float g_vn[2*384*128];
__device__ float g_ao[2*384*128];
__device__ float g_Pc[2*384*64];
__device__ float g_Pd[2*384*64];

__device__ __forceinline__ void fma2(unsigned long long &d, unsigned long long a, unsigned long long b){
    asm("fma.rn.f32x2 %0, %1, %2, %3;" : "=l"(d) : "l"(a), "l"(b), "l"(d));
}
__device__ __forceinline__ float hsum2(unsigned long long v){
    return __uint_as_float((unsigned)v) + __uint_as_float((unsigned)(v>>32));
}
__device__ __forceinline__ void bsplit(float v, unsigned short &h, unsigned short &l){
    __nv_bfloat16 bh = __float2bfloat16(v);
    float hf = __bfloat162float(bh);
    __nv_bfloat16 bl = __float2bfloat16(v - hf);
    h = *(unsigned short*)&bh; l = *(unsigned short*)&bl;
}
__device__ __forceinline__ void mma16816(float* d, const unsigned* a, const unsigned* b){
    asm volatile("mma.sync.aligned.m16n8k16.row.col.f32.bf16.bf16.f32 "
        "{%0,%1,%2,%3},{%4,%5,%6,%7},{%8,%9},{%0,%1,%2,%3};"
        : "+f"(d[0]),"+f"(d[1]),"+f"(d[2]),"+f"(d[3])
        : "r"(a[0]),"r"(a[1]),"r"(a[2]),"r"(a[3]),"r"(b[0]),"r"(b[1]));
}

// ============ k_qkv ============
#define QKV_SMEM (51744*4)
__global__ void __launch_bounds__(256) k_qkv(const float* __restrict__ x,
    const float* __restrict__ wnq, const float* __restrict__ wnk, const float* __restrict__ wnv){
    extern __shared__ float sm[];
    float* sWq = sm; float* sWk = sm + 16896; float* sWv = sm + 33792; float* sX = sm + 50688;
    int tid = threadIdx.x;
    for (int idx=tid; idx<4096; idx+=256){
        int o = idx>>5, c4 = idx&31;
        *(float4*)(sWq + o*132 + c4*4) = *(const float4*)(wnq + o*128 + c4*4);
        *(float4*)(sWk + o*132 + c4*4) = *(const float4*)(wnk + o*128 + c4*4);
        *(float4*)(sWv + o*132 + c4*4) = *(const float4*)(wnv + o*128 + c4*4);
    }
    int r0 = blockIdx.x*8;
    { int r = tid>>5, c4 = tid&31;
      *(float4*)(sX + r*132 + c4*4) = *(const float4*)(x + (size_t)(r0+r)*128 + c4*4); }
    __syncthreads();
    int o = tid&127, g = tid>>7;
    float aq[4]={0,0,0,0}, ak[4]={0,0,0,0}, av[4]={0,0,0,0};
#pragma unroll 4
    for (int c4=0;c4<32;++c4){
        float4 wq = *(const float4*)(sWq + o*132 + c4*4);
        float4 wk = *(const float4*)(sWk + o*132 + c4*4);
        float4 wv = *(const float4*)(sWv + o*132 + c4*4);
#pragma unroll
        for (int rr=0;rr<4;++rr){
            float4 a = *(const float4*)(sX + (g*4+rr)*132 + c4*4);
            aq[rr] += wq.x*a.x+wq.y*a.y+wq.z*a.z+wq.w*a.w;
            ak[rr] += wk.x*a.x+wk.y*a.y+wk.z*a.z+wk.w*a.w;
            av[rr] += wv.x*a.x+wv.y*a.y+wv.z*a.z+wv.w*a.w;
        }
    }
#pragma unroll
    for (int rr=0;rr<4;++rr){
        int r = r0 + g*4 + rr;
        g_qn[r*128+o]=aq[rr]; g_kn[r*128+o]=ak[rr]; g_vn[r*128+o]=av[rr];
    }
}

// ============ k_attn ============
#define ATTN_SMEM (22784*4)
__global__ void __launch_bounds__(256) k_attn(const float* __restrict__ adj,
    const float* __restrict__ weq, const float* __restrict__ wek, const float* __restrict__ wev){
    extern __shared__ float sm[];
    float* sW = sm; float* sA = sm + 17408; float* sS = sm + 19584; float* sQ = sm + 22656;
    int bi = blockIdx.x, b = bi/384;
    int tid = threadIdx.x;
    int to = tid&31, tp = tid>>5;
    for (int idx=tid; idx<4096; idx+=256){
        int o = idx>>4, c4 = idx&15;
        float4 v = (o<128) ? *(const float4*)(weq + o*64 + c4*4)
                           : *(const float4*)(wek + (o-128)*64 + c4*4);
        *(float4*)(sW + o*68 + c4*4) = v;
    }
    if (tid<128) sQ[tid] = g_qn[(size_t)bi*128 + tid];
    const float* adj_i = adj + (size_t)bi*24576;
    __syncthreads();
    for (int jt=0; jt<12; ++jt){
        int j0 = jt*32;
        for (int idx=tid; idx<512; idx+=256){
            int p = idx>>4, c4 = idx&15;
            *(float4*)(sA + p*68 + c4*4) = *(const float4*)(adj_i + (size_t)(j0+p)*64 + c4*4);
        }
        __syncthreads();
        unsigned long long acc[4][8];
#pragma unroll
        for (int p=0;p<4;++p)
#pragma unroll
            for (int o=0;o<8;++o) acc[p][o]=0ull;
#pragma unroll 2
        for (int c4=0;c4<16;++c4){
            ulonglong2 a[4], w[8];
#pragma unroll
            for (int k=0;k<4;++k) a[k] = *(const ulonglong2*)(sA + (tp*4+k)*68 + c4*4);
#pragma unroll
            for (int k=0;k<8;++k) w[k] = *(const ulonglong2*)(sW + (k*32+to)*68 + c4*4);
#pragma unroll
            for (int p=0;p<4;++p)
#pragma unroll
                for (int o=0;o<8;++o){ fma2(acc[p][o], a[p].x, w[o].x); fma2(acc[p][o], a[p].y, w[o].y); }
        }
#pragma unroll
        for (int pp=0;pp<4;++pp){
            int j = j0 + tp*4 + pp;
            const float* kr = g_kn + (size_t)(b*384+j)*128;
#pragma unroll
            for (int m=0;m<4;++m){
                int d = m*32 + to;
                float eq = sQ[d] + hsum2(acc[pp][m]);
                float ek = __ldg(&kr[d]) + hsum2(acc[pp][m+4]);
                float pr = eq*ek;
                pr += __shfl_xor_sync(0xffffffffu, pr, 1);
                pr += __shfl_xor_sync(0xffffffffu, pr, 2);
                pr += __shfl_xor_sync(0xffffffffu, pr, 4);
                pr += __shfl_xor_sync(0xffffffffu, pr, 8);
                if ((to&15)==0) sS[(2*m + (to>>4))*384 + j] = pr*SCALE;
            }
        }
        __syncthreads();
    }
    float* sWV = sm; float* sAW = sm + 8192; float* sOV = sm + 12288; float* sTOT= sm + 13312; float* sOVT= sm + 13824;
    for (int idx=tid; idx<8192; idx+=256) sWV[idx]=wev[idx];
    __syncthreads();
    {
        int w = tp, l = to;
        float vals[12]; float m=-1e30f;
#pragma unroll
        for (int q=0;q<12;++q){ vals[q]=sS[w*384+q*32+l]; m=fmaxf(m,vals[q]); }
#pragma unroll
        for (int off=16;off;off>>=1) m=fmaxf(m,__shfl_xor_sync(0xffffffffu,m,off));
        float Z=0.f;
#pragma unroll
        for (int q=0;q<12;++q){ vals[q]=__expf(vals[q]-m); Z+=vals[q]; }
#pragma unroll
        for (int off=16;off;off>>=1) Z+=__shfl_xor_sync(0xffffffffu,Z,off);
        float inv=1.0f/Z;
#pragma unroll
        for (int q=0;q<12;++q) sS[w*384+q*32+l]=vals[q]*inv;
    }
    __syncthreads();
    {
        int w = tp, l = to, h2l = l>>2;
        float aw0[8], aw1[8]; float4 ov = make_float4(0,0,0,0);
#pragma unroll
        for (int h=0;h<8;++h){ aw0[h]=0.f; aw1[h]=0.f; }
        for (int jj=0; jj<48; ++jj){
            int j=w*48+jj;
            float ah[8];
#pragma unroll
            for (int h=0;h<8;++h) ah[h]=sS[h*384+j];
            float2 av = ((const float2*)(adj_i + (size_t)j*64))[l];
#pragma unroll
            for (int h=0;h<8;++h){ aw0[h]+=ah[h]*av.x; aw1[h]+=ah[h]*av.y; }
            float4 vv = ((const float4*)(g_vn + (size_t)(b*384+j)*128))[l];
            float a = ah[h2l];
            ov.x+=a*vv.x; ov.y+=a*vv.y; ov.z+=a*vv.z; ov.w+=a*vv.w;
        }
#pragma unroll
        for (int h=0;h<8;++h){ sAW[(w*8+h)*64 + 2*l]=aw0[h]; sAW[(w*8+h)*64 + 2*l+1]=aw1[h]; }
        ((float4*)(sOV + w*128))[l]=ov;
    }
    __syncthreads();
    for (int idx=tid; idx<512; idx+=256){
        float s=0.f;
#pragma unroll
        for (int w2=0;w2<8;++w2) s+=sAW[w2*512+idx];
        sTOT[idx]=s;
    }
    if (tid<128){
        float s=0.f;
#pragma unroll
        for (int w2=0;w2<8;++w2) s+=sOV[w2*128+tid];
        sOVT[tid]=s;
    }
    __syncthreads();
    if (tid<128){
        int h=tid>>4;
        float acc=sOVT[tid];
#pragma unroll 8
        for (int c=0;c<64;++c){
            int cc=(c+tid)&63;
            acc += sWV[tid*64+cc]*sTOT[h*64+cc];
        }
        g_ao[(size_t)bi*128 + (tid&15)*8 + h] = acc;
    }
}

// ============ k_node ============
#define NODE_SMEM (40160*4)
__global__ void __launch_bounds__(256) k_node(const float* __restrict__ x,
    const float* __restrict__ nfc1_w, const float* __restrict__ nfc1_b,
    const float* __restrict__ ln1_g, const float* __restrict__ ln1_b,
    const float* __restrict__ nfc2_w, const float* __restrict__ nfc2_b,
    const float* __restrict__ nfc3_w, const float* __restrict__ nfc3_b,
    const float* __restrict__ ln2_g, const float* __restrict__ ln2_b,
    const float* __restrict__ efc1_w, float* __restrict__ out_x){
    extern __shared__ float sm[];
    float* sW  = sm; float* sao = sm + 33792; float* sx = sm + 34848; float* sx1 = sm + 35904;
    float* sh  = sm + 36960; float* sx2 = sm + 39040; float* sred= sm + 40096;
    int tid = threadIdx.x;
    int o = tid&127, g = tid>>7;
    int l = tid&31, wg = (tid>>5)&3;
    int r0 = blockIdx.x*8;
    { int r = tid>>5, c4 = tid&31;
      *(float4*)(sx  + r*132 + c4*4) = *(const float4*)(x    + (size_t)(r0+r)*128 + c4*4);
      *(float4*)(sao + r*132 + c4*4) = *(const float4*)(g_ao + (size_t)(r0+r)*128 + c4*4); }
    for (int idx=tid; idx<4096; idx+=256){
        int oo=idx>>5, c4=idx&31;
        *(float4*)(sW + oo*132 + c4*4) = *(const float4*)(nfc1_w + oo*128 + c4*4);
    }
    __syncthreads();
    float val[4];
    {
        float acc[4]; float bv = __ldg(&nfc1_b[o]);
#pragma unroll
        for (int rr=0;rr<4;++rr) acc[rr]=bv;
#pragma unroll 4
        for (int c4=0;c4<32;++c4){
            float4 w = *(const float4*)(sW + o*132 + c4*4);
#pragma unroll
            for (int rr=0;rr<4;++rr){
                float4 a = *(const float4*)(sao + (g*4+rr)*132 + c4*4);
                acc[rr] += w.x*a.x+w.y*a.y+w.z*a.z+w.w*a.w;
            }
        }
#pragma unroll
        for (int rr=0;rr<4;++rr) val[rr] = sx[(g*4+rr)*132+o] + acc[rr];
    }
#pragma unroll
    for (int rr=0;rr<4;++rr){
        float s=val[rr], s2=val[rr]*val[rr];
#pragma unroll
        for (int off=16;off;off>>=1){ s+=__shfl_xor_sync(0xffffffffu,s,off); s2+=__shfl_xor_sync(0xffffffffu,s2,off); }
        if (l==0){ sred[(g*4+rr)*8 + wg*2]=s; sred[(g*4+rr)*8 + wg*2+1]=s2; }
    }
    __syncthreads();
#pragma unroll
    for (int rr=0;rr<4;++rr){
        int r = g*4+rr;
        float S = sred[r*8]+sred[r*8+2]+sred[r*8+4]+sred[r*8+6];
        float S2= sred[r*8+1]+sred[r*8+3]+sred[r*8+5]+sred[r*8+7];
        float m = S*(1.f/128.f), var = S2*(1.f/128.f)-m*m, rs = rsqrtf(var+EPSF);
        sx1[r*132+o] = (val[rr]-m)*rs*__ldg(&ln1_g[o])+__ldg(&ln1_b[o]);
    }
    __syncthreads();
    for (int idx=tid; idx<8192; idx+=256){
        int oo=idx>>5, c4=idx&31;
        *(float4*)(sW + oo*132 + c4*4) = *(const float4*)(nfc2_w + oo*128 + c4*4);
    }
    __syncthreads();
    {
        float a0[4], a1[4];
        float b0=__ldg(&nfc2_b[o]), b1=__ldg(&nfc2_b[o+128]);
#pragma unroll
        for (int rr=0;rr<4;++rr){ a0[rr]=b0; a1[rr]=b1; }
#pragma unroll 4
        for (int c4=0;c4<32;++c4){
            float4 w0 = *(const float4*)(sW + o*132 + c4*4);
            float4 w1 = *(const float4*)(sW + (o+128)*132 + c4*4);
#pragma unroll
            for (int rr=0;rr<4;++rr){
                float4 a = *(const float4*)(sx1 + (g*4+rr)*132 + c4*4);
                a0[rr] += w0.x*a.x+w0.y*a.y+w0.z*a.z+w0.w*a.w;
                a1[rr] += w1.x*a.x+w1.y*a.y+w1.z*a.z+w1.w*a.w;
            }
        }
#pragma unroll
        for (int rr=0;rr<4;++rr){
            sh[(g*4+rr)*260 + o]       = fmaxf(a0[rr],0.f);
            sh[(g*4+rr)*260 + 128 + o] = fmaxf(a1[rr],0.f);
        }
    }
    __syncthreads();
    for (int idx=tid; idx<8192; idx+=256){
        int oo=idx>>6, c4=idx&63;
        *(float4*)(sW + oo*260 + c4*4) = *(const float4*)(nfc3_w + oo*256 + c4*4);
    }
    __syncthreads();
    {
        float acc[4]; float bv=__ldg(&nfc3_b[o]);
#pragma unroll
        for (int rr=0;rr<4;++rr) acc[rr]=bv;
#pragma unroll 4
        for (int c4=0;c4<64;++c4){
            float4 w = *(const float4*)(sW + o*260 + c4*4);
#pragma unroll
            for (int rr=0;rr<4;++rr){
                float4 a = *(const float4*)(sh + (g*4+rr)*260 + c4*4);
                acc[rr] += w.x*a.x+w.y*a.y+w.z*a.z+w.w*a.w;
            }
        }
#pragma unroll
        for (int rr=0;rr<4;++rr) val[rr] = sx1[(g*4+rr)*132+o] + acc[rr];
    }
#pragma unroll
    for (int rr=0;rr<4;++rr){
        float s=val[rr], s2=val[rr]*val[rr];
#pragma unroll
        for (int off=16;off;off>>=1){ s+=__shfl_xor_sync(0xffffffffu,s,off); s2+=__shfl_xor_sync(0xffffffffu,s2,off); }
        if (l==0){ sred[(g*4+rr)*8 + wg*2]=s; sred[(g*4+rr)*8 + wg*2+1]=s2; }
    }
    __syncthreads();
#pragma unroll
    for (int rr=0;rr<4;++rr){
        int r = g*4+rr;
        float S = sred[r*8]+sred[r*8+2]+sred[r*8+4]+sred[r*8+6];
        float S2= sred[r*8+1]+sred[r*8+3]+sred[r*8+5]+sred[r*8+7];
        float m = S*(1.f/128.f), var = S2*(1.f/128.f)-m*m, rs = rsqrtf(var+EPSF);
        float x2v = (val[rr]-m)*rs*__ldg(&ln2_g[o])+__ldg(&ln2_b[o]);
        sx2[r*132+o] = x2v;
        out_x[(size_t)(r0+r)*128+o] = x2v;
    }
    __syncthreads();
    for (int idx=tid; idx<4096; idx+=256){
        int o2=idx>>5, c4=idx&31;
        float4 v = (o2<64) ? *(const float4*)(efc1_w + o2*384 + 128 + c4*4)
                           : *(const float4*)(efc1_w + (o2-64)*384 + 256 + c4*4);
        *(float4*)(sW + o2*132 + c4*4) = v;
    }
    __syncthreads();
    {
        float acc[4]={0,0,0,0};
#pragma unroll 4
        for (int c4=0;c4<32;++c4){
            float4 w = *(const float4*)(sW + o*132 + c4*4);
#pragma unroll
            for (int rr=0;rr<4;++rr){
                float4 a = *(const float4*)(sx2 + (g*4+rr)*132 + c4*4);
                acc[rr] += w.x*a.x+w.y*a.y+w.z*a.z+w.w*a.w;
            }
        }
#pragma unroll
        for (int rr=0;rr<4;++rr){
            int r = r0 + g*4 + rr;
            if (o<64) g_Pc[(size_t)r*64+o]=acc[rr];
            else      g_Pd[(size_t)r*64+(o-64)]=acc[rr];
        }
    }
}

// ============ k_edge3: mma.sync bf16-split, CTA=(b,i,64j), 256 thr ============
// bytes: sWh 18432 @0 | sWl @18432 | A0-A3 (64x72 u16 = 9216) @36864,46080,55296,64512
//      | sD (64x68 f32) @73728 | sY @91136 | sB(640 f32) @108544  => 111104
#define EDGE3_SMEM 111104
typedef unsigned short us16;

__device__ __forceinline__ void gemm_unit(const us16* Ah, const us16* Al,
    const us16* Wh, const us16* Wl, float d[2][2][4], int wm, int wn, int g, int q){
#pragma unroll
    for (int k=0;k<4;++k){
        int K0 = k*16;
        unsigned ah[2][4], al_[2][4], bh[2][2], bl[2][2];
#pragma unroll
        for (int mt=0;mt<2;++mt){
            const us16* p  = Ah + (wm*32 + mt*16 + g)*72 + K0 + 2*q;
            const us16* pl = Al + (wm*32 + mt*16 + g)*72 + K0 + 2*q;
            ah[mt][0]=*(const unsigned*)p;      ah[mt][1]=*(const unsigned*)(p+576);
            ah[mt][2]=*(const unsigned*)(p+8);  ah[mt][3]=*(const unsigned*)(p+584);
            al_[mt][0]=*(const unsigned*)pl;     al_[mt][1]=*(const unsigned*)(pl+576);
            al_[mt][2]=*(const unsigned*)(pl+8); al_[mt][3]=*(const unsigned*)(pl+584);
        }
#pragma unroll
        for (int nt=0;nt<2;++nt){
            const us16* p  = Wh + (wn*16 + nt*8 + g)*72 + K0 + 2*q;
            const us16* pl = Wl + (wn*16 + nt*8 + g)*72 + K0 + 2*q;
            bh[nt][0]=*(const unsigned*)p;  bh[nt][1]=*(const unsigned*)(p+8);
            bl[nt][0]=*(const unsigned*)pl; bl[nt][1]=*(const unsigned*)(pl+8);
        }
#pragma unroll
        for (int mt=0;mt<2;++mt)
#pragma unroll
            for (int nt=0;nt<2;++nt){
                mma16816(d[mt][nt], ah[mt], bh[nt]);
                mma16816(d[mt][nt], ah[mt], bl[nt]);
                mma16816(d[mt][nt], al_[mt], bh[nt]);
            }
    }
}
__device__ __forceinline__ void store_d(float d[2][2][4], float* sD, int wm, int wn, int g, int q){
#pragma unroll
    for (int mt=0;mt<2;++mt)
#pragma unroll
        for (int nt=0;nt<2;++nt){
            int r = wm*32 + mt*16 + g, c = wn*16 + nt*8 + 2*q;
            *(float2*)(sD + r*68 + c)     = make_float2(d[mt][nt][0], d[mt][nt][1]);
            *(float2*)(sD + (r+8)*68 + c) = make_float2(d[mt][nt][2], d[mt][nt][3]);
        }
}
__device__ __forceinline__ void zero_d(float d[2][2][4]){
#pragma unroll
    for (int mt=0;mt<2;++mt)
#pragma unroll
        for (int nt=0;nt<2;++nt)
#pragma unroll
            for (int e=0;e<4;++e) d[mt][nt][e]=0.f;
}

__global__ void __launch_bounds__(256) k_edge3(const float* __restrict__ adj,
    const float* __restrict__ efc1_w, const float* __restrict__ efc1_b,
    const float* __restrict__ efc2_w, const float* __restrict__ efc2_b,
    const float* __restrict__ eg1, const float* __restrict__ eb1,
    const float* __restrict__ efc3_w, const float* __restrict__ efc3_b,
    const float* __restrict__ efc4_w, const float* __restrict__ efc4_b,
    const float* __restrict__ eg2, const float* __restrict__ eb2,
    float* __restrict__ out_adj){
    extern __shared__ char smE[];
    us16* sWh = (us16*)smE;
    us16* sWl = (us16*)(smE+18432);
    us16* A0 = (us16*)(smE+36864);
    us16* A1 = (us16*)(smE+46080);
    us16* A2 = (us16*)(smE+55296);
    us16* A3 = (us16*)(smE+64512);
    float* sD = (float*)(smE+73728);
    float* sY = (float*)(smE+91136);
    float* sB = (float*)(smE+108544);
    int tid = threadIdx.x;
    int lane = tid&31, wid = tid>>5;
    int g = lane>>2, q = lane&3;
    int wm = wid>>2, wn = wid&3;
    int tp = tid>>4, to = tid&15;
    int bx = blockIdx.x;
    int bi = bx/6, jt = bx - bi*6;
    int b = bi/384, i = bi - b*384;
    int j0 = jt*64;
    const float* adjb = adj + (size_t)b*9437184;

    // init: activations + W1 + biases
    for (int idx=tid; idx<4096; idx+=256){
        int p = idx>>6, c = idx&63;
        us16 h,l;
        bsplit(adjb[((size_t)i*384 + j0+p)*64 + c], h, l);
        A0[p*72+c]=h; A1[p*72+c]=l;
        bsplit(adjb[((size_t)(j0+p)*384 + i)*64 + c], h, l);
        A2[p*72+c]=h; A3[p*72+c]=l;
    }
    for (int idx=tid; idx<8192; idx+=256){
        int r = idx>>6, c = idx&63;
        float v = (r<64) ? efc1_w[r*384+c] : efc1_w[(r-64)*384+64+c];
        us16 h,l; bsplit(v,h,l);
        sWh[r*72+c]=h; sWl[r*72+c]=l;
    }
    if (tid<64){
        sB[tid]=efc1_b[tid]; sB[64+tid]=efc2_b[tid]; sB[256+tid]=efc4_b[tid];
        sB[320+tid]=eg1[tid]; sB[384+tid]=eb1[tid]; sB[448+tid]=eg2[tid]; sB[512+tid]=eb2[tid];
        sB[576+tid]=g_Pd[(size_t)bi*64+tid];
    }
    if (tid<128) sB[128+tid]=efc3_b[tid];
    __syncthreads();

    float d[2][2][4];
    // stage 1: ai*W1a + aj*W1b
    zero_d(d);
    gemm_unit(A0, A1, sWh, sWl, d, wm, wn, g, q);
    gemm_unit(A2, A3, sWh + 64*72, sWl + 64*72, d, wm, wn, g, q);
    store_d(d, sD, wm, wn, g, q);
    __syncthreads();
    // epi1 -> h1 in A2/A3 ; load W2 rows 0-63
    {
        const float* pc = g_Pc + ((size_t)b*384 + j0)*64;
#pragma unroll
        for (int p=0;p<4;++p){
            int pr = tp*4+p;
#pragma unroll
            for (int oo=0;oo<4;++oo){
                int o = oo*16+to;
                float h = sD[pr*68+o] + sB[o] + sB[576+o] + __ldg(&pc[pr*64+o]);
                h = fmaxf(h, 0.f);
                us16 hh,ll; bsplit(h,hh,ll);
                A2[pr*72+o]=hh; A3[pr*72+o]=ll;
            }
        }
        for (int idx=tid; idx<4096; idx+=256){
            int o = idx>>6, c = idx&63;
            us16 hh,ll; bsplit(efc2_w[o*64+c],hh,ll);
            sWh[o*72+c]=hh; sWl[o*72+c]=ll;
        }
    }
    __syncthreads();
    // stage 2: h1*W2
    zero_d(d);
    gemm_unit(A2, A3, sWh, sWl, d, wm, wn, g, q);
    store_d(d, sD, wm, wn, g, q);
    __syncthreads();
    // epi2 -> y: LN(ai + D + b2) -> sY fp32, A0/A1 bf16 ; load W3 (128 rows)
    {
#pragma unroll
        for (int p=0;p<4;++p){
            int pr = tp*4+p;
            float v[4], s=0.f, s2=0.f;
#pragma unroll
            for (int oo=0;oo<4;++oo){
                int o = oo*16+to;
                v[oo] = sD[pr*68+o] + sB[64+o] + __ldg(&adjb[((size_t)i*384 + j0+pr)*64 + o]);
                s += v[oo]; s2 += v[oo]*v[oo];
            }
            s  += __shfl_xor_sync(0xffffffffu,s,1);  s2 += __shfl_xor_sync(0xffffffffu,s2,1);
            s  += __shfl_xor_sync(0xffffffffu,s,2);  s2 += __shfl_xor_sync(0xffffffffu,s2,2);
            s  += __shfl_xor_sync(0xffffffffu,s,4);  s2 += __shfl_xor_sync(0xffffffffu,s2,4);
            s  += __shfl_xor_sync(0xffffffffu,s,8);  s2 += __shfl_xor_sync(0xffffffffu,s2,8);
            float m = s*(1.f/64.f), var = s2*(1.f/64.f)-m*m, rs = rsqrtf(var+EPSF);
#pragma unroll
            for (int oo=0;oo<4;++oo){
                int o = oo*16+to;
                float y = (v[oo]-m)*rs*sB[320+o]+sB[384+o];
                sY[pr*68+o] = y;
                us16 hh,ll; bsplit(y,hh,ll);
                A0[pr*72+o]=hh; A1[pr*72+o]=ll;
            }
        }
        for (int idx=tid; idx<8192; idx+=256){
            int r = idx>>6, c = idx&63;
            us16 hh,ll; bsplit(efc3_w[r*64+c],hh,ll);
            sWh[r*72+c]=hh; sWl[r*72+c]=ll;
        }
    }
    __syncthreads();
    // stage 3 pass 1: y*W3[0:64]
    zero_d(d);
    gemm_unit(A0, A1, sWh, sWl, d, wm, wn, g, q);
    store_d(d, sD, wm, wn, g, q);
    __syncthreads();
    // epi3a -> h3lo in A2/A3
#pragma unroll
    for (int p=0;p<4;++p){
        int pr = tp*4+p;
#pragma unroll
        for (int oo=0;oo<4;++oo){
            int o = oo*16+to;
            float h = fmaxf(sD[pr*68+o] + sB[128+o], 0.f);
            us16 hh,ll; bsplit(h,hh,ll);
            A2[pr*72+o]=hh; A3[pr*72+o]=ll;
        }
    }
    __syncthreads();
    // stage 3 pass 2: y*W3[64:128]
    zero_d(d);
    gemm_unit(A0, A1, sWh + 64*72, sWl + 64*72, d, wm, wn, g, q);
    store_d(d, sD, wm, wn, g, q);
    __syncthreads();
    // epi3b -> h3hi in A0/A1 ; load W4 (lo rows 0-63, hi rows 64-127)
    {
#pragma unroll
        for (int p=0;p<4;++p){
            int pr = tp*4+p;
#pragma unroll
            for (int oo=0;oo<4;++oo){
                int o = oo*16+to;
                float h = fmaxf(sD[pr*68+o] + sB[192+o], 0.f);
                us16 hh,ll; bsplit(h,hh,ll);
                A0[pr*72+o]=hh; A1[pr*72+o]=ll;
            }
        }
        for (int idx=tid; idx<8192; idx+=256){
            int o = idx>>7, c = idx&127;
            int ch = c>>6, cc = c&63;
            us16 hh,ll; bsplit(efc4_w[o*128+c],hh,ll);
            sWh[(ch*64+o)*72+cc]=hh; sWl[(ch*64+o)*72+cc]=ll;
        }
    }
    __syncthreads();
    // stage 4: h3lo*W4lo + h3hi*W4hi
    zero_d(d);
    gemm_unit(A2, A3, sWh, sWl, d, wm, wn, g, q);
    gemm_unit(A0, A1, sWh + 64*72, sWl + 64*72, d, wm, wn, g, q);
    store_d(d, sD, wm, wn, g, q);
    __syncthreads();
    // epi4: out = LN(y + D + b4)
#pragma unroll
    for (int p=0;p<4;++p){
        int pr = tp*4+p;
        float v[4], s=0.f, s2=0.f;
#pragma unroll
        for (int oo=0;oo<4;++oo){
            int o = oo*16+to;
            v[oo] = sD[pr*68+o] + sB[256+o] + sY[pr*68+o];
            s += v[oo]; s2 += v[oo]*v[oo];
        }
        s  += __shfl_xor_sync(0xffffffffu,s,1);  s2 += __shfl_xor_sync(0xffffffffu,s2,1);
        s  += __shfl_xor_sync(0xffffffffu,s,2);  s2 += __shfl_xor_sync(0xffffffffu,s2,2);
        s  += __shfl_xor_sync(0xffffffffu,s,4);  s2 += __shfl_xor_sync(0xffffffffu,s2,4);
        s  += __shfl_xor_sync(0xffffffffu,s,8);  s2 += __shfl_xor_sync(0xffffffffu,s2,8);
        float m = s*(1.f/64.f), var = s2*(1.f/64.f)-m*m, rs = rsqrtf(var+EPSF);
#pragma unroll
        for (int oo=0;oo<4;++oo){
            int o = oo*16+to;
            out_adj[((size_t)bi*384 + j0+pr)*64 + o] = (v[oo]-m)*rs*sB[448+o]+sB[512+o];
        }
    }
}

extern "C" void kernel_launch(void* const* d_in, const int* in_sizes, int n_in,
                              void* d_out, int out_size){
    const float* x   = (const float*)d_in[0];
    const float* adj = (const float*)d_in[1];
    float* out_x   = (float*)d_out;
    float* out_adj = out_x + 2*384*128;

    cudaFuncSetAttribute(k_qkv,  cudaFuncAttributeMaxDynamicSharedMemorySize, QKV_SMEM);
    cudaFuncSetAttribute(k_attn, cudaFuncAttributeMaxDynamicSharedMemorySize, ATTN_SMEM);
    cudaFuncSetAttribute(k_node, cudaFuncAttributeMaxDynamicSharedMemorySize, NODE_SMEM);
    cudaFuncSetAttribute(k_edge3, cudaFuncAttributeMaxDynamicSharedMemorySize, EDGE3_SMEM);

    k_qkv<<<96,256,QKV_SMEM>>>(x, (const float*)d_in[2], (const float*)d_in[3], (const float*)d_in[4]);
    k_attn<<<768,256,ATTN_SMEM>>>(adj, (const float*)d_in[5], (const float*)d_in[6], (const float*)d_in[7]);
    k_node<<<96,256,NODE_SMEM>>>(x, (const float*)d_in[8], (const float*)d_in[9],
        (const float*)d_in[10], (const float*)d_in[11], (const float*)d_in[12], (const float*)d_in[13],
        (const float*)d_in[14], (const float*)d_in[15], (const float*)d_in[16], (const float*)d_in[17],
        (const float*)d_in[18], out_x);
    k_edge3<<<4608,256,EDGE3_SMEM>>>(adj, (const float*)d_in[18], (const float*)d_in[19],
        (const float*)d_in[20], (const float*)d_in[21], (const float*)d_in[22], (const float*)d_in[23],
        (const float*)d_in[24], (const float*)d_in[25], (const float*)d_in[26], (const float*)d_in[27],
        (const float*)d_in[28], (const float*)d_in[29], out_adj);
}